// round 3
// baseline (speedup 1.0000x reference)
#include <cuda_runtime.h>
#include <math.h>

// ---------------------------------------------------------------------------
// N=90000, D=H=128, 2H=256, E=1.44M, G=3000, P=675000.
// ---------------------------------------------------------------------------
#define MAXN 90112
#define MAXG 4096

__device__ float g_agg [MAXN * 128];   // 46 MB
__device__ float g_ht  [MAXN * 512];   // 184 MB (holds [N,256] or combined [N,512])
__device__ float g_h1  [MAXN * 128];
__device__ float g_h2  [MAXN * 128];
__device__ float g_mean[MAXN * 128];
__device__ float g_ls  [MAXN * 128];
__device__ float g_u   [MAXN];
__device__ float g_v   [MAXN];
__device__ float g_colsum[512];
__device__ float g_colsq [512];
__device__ float g_scale [512];
__device__ float g_shift [512];
__device__ float g_pool[MAXG];
__device__ float g_cnt [MAXG];
__device__ float g_acc [2];            // [0]=kl sum, [1]=numloss sum

// ---------------------------------------------------------------------------
// Edge scatter: agg[dst] += x[src].  One warp per edge, vector red.
// ---------------------------------------------------------------------------
__global__ void scatter_k(const float* __restrict__ X,
                          const int* __restrict__ ei, int E) {
    int gw   = (blockIdx.x * blockDim.x + threadIdx.x) >> 5;
    int lane = threadIdx.x & 31;
    if (gw >= E) return;
    int s = __ldg(ei + gw);
    int d = __ldg(ei + E + gw);
    float4 vv = *(const float4*)(X + (size_t)s * 128 + lane * 4);
    float* dst = g_agg + (size_t)d * 128 + lane * 4;
    asm volatile("red.global.add.v4.f32 [%0], {%1,%2,%3,%4};"
                 :: "l"(dst), "f"(vv.x), "f"(vv.y), "f"(vv.z), "f"(vv.w)
                 : "memory");
}

// ---------------------------------------------------------------------------
// GEMM1: OUT[N,ldo] tile = (X + AGG)[N,128] @ W[128,ncols] + bias
// 128x128 block tile, 256 threads, 8x8 microtile, BK=16.
// Fused epilogue: per-column sum & sumsq accumulated into g_colsum/g_colsq.
// Wa used for n0<256, Wb for n0>=256 (combined mean/logstd pass).
// ---------------------------------------------------------------------------
#define BM 128
#define BN 128
#define BK 16
#define LDA (BM + 4)

__global__ void __launch_bounds__(256) gemm1_k(
    const float* __restrict__ X, const float* __restrict__ Wa,
    const float* __restrict__ Wb, const float* __restrict__ bias,
    float* __restrict__ OUT, int N, int ldo) {
    __shared__ float As[BK][LDA];
    __shared__ float Ws[BK][LDA];
    int tid  = threadIdx.x;
    int row0 = blockIdx.y * BM;
    int n0   = blockIdx.x * BN;
    const float* W = (n0 < 256) ? Wa : Wb;
    int nbase = (n0 < 256) ? n0 : (n0 - 256);
    int tx = tid & 15, ty = tid >> 4;
    int ar = tid >> 2;            // 0..63
    int ac = (tid & 3) * 4;       // 0,4,8,12
    int wr = tid >> 5;            // 0..7
    int wc = (tid & 31) * 4;      // 0..124
    float acc[8][8] = {};

    for (int kk = 0; kk < 128; kk += BK) {
        #pragma unroll
        for (int h = 0; h < 2; h++) {
            int m  = ar + h * 64;
            int rg = row0 + m;
            float4 a = make_float4(0.f, 0.f, 0.f, 0.f);
            if (rg < N) {
                size_t off = (size_t)rg * 128 + kk + ac;
                float4 xv = *(const float4*)(X + off);
                float4 av = *(const float4*)(g_agg + off);
                a.x = xv.x + av.x; a.y = xv.y + av.y;
                a.z = xv.z + av.z; a.w = xv.w + av.w;
            }
            As[ac + 0][m] = a.x; As[ac + 1][m] = a.y;
            As[ac + 2][m] = a.z; As[ac + 3][m] = a.w;
        }
        #pragma unroll
        for (int h = 0; h < 2; h++) {
            int k = wr + h * 8;
            *(float4*)&Ws[k][wc] =
                *(const float4*)(W + (size_t)(kk + k) * 256 + nbase + wc);
        }
        __syncthreads();
        #pragma unroll
        for (int k = 0; k < BK; k++) {
            float a[8], w[8];
            *(float4*)(a)     = *(float4*)&As[k][ty * 8];
            *(float4*)(a + 4) = *(float4*)&As[k][ty * 8 + 4];
            *(float4*)(w)     = *(float4*)&Ws[k][tx * 8];
            *(float4*)(w + 4) = *(float4*)&Ws[k][tx * 8 + 4];
            #pragma unroll
            for (int i = 0; i < 8; i++)
                #pragma unroll
                for (int j = 0; j < 8; j++)
                    acc[i][j] += a[i] * w[j];
        }
        __syncthreads();
    }

    float bcol[8];
    *(float4*)(bcol)     = *(const float4*)(bias + n0 + tx * 8);
    *(float4*)(bcol + 4) = *(const float4*)(bias + n0 + tx * 8 + 4);
    float ps[8] = {}, pq[8] = {};
    #pragma unroll
    for (int i = 0; i < 8; i++) {
        int rg = row0 + ty * 8 + i;
        if (rg < N) {
            float o[8];
            #pragma unroll
            for (int j = 0; j < 8; j++) {
                o[j] = acc[i][j] + bcol[j];
                ps[j] += o[j];
                pq[j] += o[j] * o[j];
            }
            float* dst = OUT + (size_t)rg * ldo + n0 + tx * 8;
            *(float4*)(dst)     = *(float4*)(o);
            *(float4*)(dst + 4) = *(float4*)(o + 4);
        }
    }
    // block reduce column partials (16 ty-groups -> 1), then global atomics
    float* red = &As[0][0];  // 2112 floats available, need 2048
    __syncthreads();
    #pragma unroll
    for (int j = 0; j < 8; j++) red[ty * 128 + tx * 8 + j] = ps[j];
    __syncthreads();
    if (tid < 128) {
        float s = 0.f;
        #pragma unroll
        for (int r = 0; r < 16; r++) s += red[r * 128 + tid];
        atomicAdd(&g_colsum[n0 + tid], s);
    }
    __syncthreads();
    #pragma unroll
    for (int j = 0; j < 8; j++) red[ty * 128 + tx * 8 + j] = pq[j];
    __syncthreads();
    if (tid < 128) {
        float s = 0.f;
        #pragma unroll
        for (int r = 0; r < 16; r++) s += red[r * 128 + tid];
        atomicAdd(&g_colsq[n0 + tid], s);
    }
}

// BN finalize: scale/shift per column (C threads).
__global__ void bnfin_k(const float* __restrict__ gamma,
                        const float* __restrict__ beta, int N) {
    int c = blockIdx.x * blockDim.x + threadIdx.x;
    float invN = 1.0f / (float)N;
    float mu  = g_colsum[c] * invN;
    float var = g_colsq[c] * invN - mu * mu;
    float sc  = gamma[c] * rsqrtf(var + 1e-5f);
    g_scale[c] = sc;
    g_shift[c] = beta[c] - mu * sc;
}

// ---------------------------------------------------------------------------
// GEMM2: OUT[N,128] = BN(HT[:, koff:koff+256])[N,256] @ W[256,128] + b2
// (optional ReLU applied to BN output). Same 128x128 tiling.
// ---------------------------------------------------------------------------
__global__ void __launch_bounds__(256) gemm2_k(
    const float* __restrict__ HT, const float* __restrict__ W,
    const float* __restrict__ bias, float* __restrict__ OUT,
    int N, int ldh, int koff, int relu) {
    __shared__ float As[BK][LDA];
    __shared__ float Ws[BK][LDA];
    int tid  = threadIdx.x;
    int row0 = blockIdx.y * BM;
    int n0   = blockIdx.x * BN;
    int tx = tid & 15, ty = tid >> 4;
    int ar = tid >> 2;
    int ac = (tid & 3) * 4;
    int wr = tid >> 5;
    int wc = (tid & 31) * 4;
    float acc[8][8] = {};

    for (int kk = 0; kk < 256; kk += BK) {
        float4 sc4 = *(const float4*)(g_scale + koff + kk + ac);
        float4 sh4 = *(const float4*)(g_shift + koff + kk + ac);
        #pragma unroll
        for (int h = 0; h < 2; h++) {
            int m  = ar + h * 64;
            int rg = row0 + m;
            float4 a = make_float4(0.f, 0.f, 0.f, 0.f);
            if (rg < N) {
                float4 h4 = *(const float4*)(HT + (size_t)rg * ldh + koff + kk + ac);
                a.x = h4.x * sc4.x + sh4.x;
                a.y = h4.y * sc4.y + sh4.y;
                a.z = h4.z * sc4.z + sh4.z;
                a.w = h4.w * sc4.w + sh4.w;
                if (relu) {
                    a.x = fmaxf(a.x, 0.f); a.y = fmaxf(a.y, 0.f);
                    a.z = fmaxf(a.z, 0.f); a.w = fmaxf(a.w, 0.f);
                }
            }
            As[ac + 0][m] = a.x; As[ac + 1][m] = a.y;
            As[ac + 2][m] = a.z; As[ac + 3][m] = a.w;
        }
        #pragma unroll
        for (int h = 0; h < 2; h++) {
            int k = wr + h * 8;
            *(float4*)&Ws[k][wc] =
                *(const float4*)(W + (size_t)(kk + k) * 128 + n0 + wc);
        }
        __syncthreads();
        #pragma unroll
        for (int k = 0; k < BK; k++) {
            float a[8], w[8];
            *(float4*)(a)     = *(float4*)&As[k][ty * 8];
            *(float4*)(a + 4) = *(float4*)&As[k][ty * 8 + 4];
            *(float4*)(w)     = *(float4*)&Ws[k][tx * 8];
            *(float4*)(w + 4) = *(float4*)&Ws[k][tx * 8 + 4];
            #pragma unroll
            for (int i = 0; i < 8; i++)
                #pragma unroll
                for (int j = 0; j < 8; j++)
                    acc[i][j] += a[i] * w[j];
        }
        __syncthreads();
    }

    float bcol[8];
    *(float4*)(bcol)     = *(const float4*)(bias + n0 + tx * 8);
    *(float4*)(bcol + 4) = *(const float4*)(bias + n0 + tx * 8 + 4);
    #pragma unroll
    for (int i = 0; i < 8; i++) {
        int rg = row0 + ty * 8 + i;
        if (rg < N) {
            float o[8];
            #pragma unroll
            for (int j = 0; j < 8; j++) o[j] = acc[i][j] + bcol[j];
            float* dst = OUT + (size_t)rg * 128 + n0 + tx * 8;
            *(float4*)(dst)     = *(float4*)(o);
            *(float4*)(dst + 4) = *(float4*)(o + 4);
        }
    }
}

// ---------------------------------------------------------------------------
// z epilogue: u=z.Wc[:128], v=z.Wc[128:], s=z.Wn, pooled sums, KL partials.
// ---------------------------------------------------------------------------
__global__ void z_k(const float* __restrict__ MEAN, const float* __restrict__ LS,
                    const float* __restrict__ NOISE, const int* __restrict__ batch,
                    const float* __restrict__ Wn, const float* __restrict__ Wc,
                    int N) {
    __shared__ float klred[8];
    int lane = threadIdx.x & 31;
    int w    = threadIdx.x >> 5;
    int row  = blockIdx.x * 8 + w;
    float klp = 0.f;
    if (row < N) {
        size_t off = (size_t)row * 128 + lane * 4;
        float4 m4 = *(const float4*)(MEAN + off);
        float4 l4 = *(const float4*)(LS + off);
        float4 n4 = *(const float4*)(NOISE + off);
        float4 e4 = make_float4(expf(l4.x), expf(l4.y), expf(l4.z), expf(l4.w));
        float4 z4 = make_float4(n4.x * e4.x + m4.x, n4.y * e4.y + m4.y,
                                n4.z * e4.z + m4.z, n4.w * e4.w + m4.w);
        float4 wa = *(const float4*)(Wc + lane * 4);
        float4 wb = *(const float4*)(Wc + 128 + lane * 4);
        float4 wn = *(const float4*)(Wn + lane * 4);
        float up = z4.x * wa.x + z4.y * wa.y + z4.z * wa.z + z4.w * wa.w;
        float vp = z4.x * wb.x + z4.y * wb.y + z4.z * wb.z + z4.w * wb.w;
        float sp = z4.x * wn.x + z4.y * wn.y + z4.z * wn.z + z4.w * wn.w;
        klp = (1.f + 2.f * l4.x - m4.x * m4.x - e4.x * e4.x)
            + (1.f + 2.f * l4.y - m4.y * m4.y - e4.y * e4.y)
            + (1.f + 2.f * l4.z - m4.z * m4.z - e4.z * e4.z)
            + (1.f + 2.f * l4.w - m4.w * m4.w - e4.w * e4.w);
        #pragma unroll
        for (int o = 16; o > 0; o >>= 1) {
            up  += __shfl_xor_sync(0xffffffffu, up,  o);
            vp  += __shfl_xor_sync(0xffffffffu, vp,  o);
            sp  += __shfl_xor_sync(0xffffffffu, sp,  o);
            klp += __shfl_xor_sync(0xffffffffu, klp, o);
        }
        if (lane == 0) {
            g_u[row] = up;
            g_v[row] = vp;
            int b = batch[row];
            atomicAdd(&g_pool[b], sp);
            atomicAdd(&g_cnt[b], 1.0f);
        }
    }
    if (lane == 0) klred[w] = (row < N) ? klp : 0.f;
    __syncthreads();
    if (threadIdx.x == 0) {
        float t = 0.f;
        #pragma unroll
        for (int i = 0; i < 8; i++) t += klred[i];
        atomicAdd(&g_acc[0], t);
    }
}

__global__ void num_k(const float* __restrict__ bridge_num,
                      const float* __restrict__ bnp,
                      float* __restrict__ out_np, int G) {
    __shared__ float red[256];
    int g = blockIdx.x * 256 + threadIdx.x;
    float d = 0.f;
    if (g < G) {
        float np = g_pool[g] / g_cnt[g] + bnp[0];
        out_np[g] = np;
        d = fabsf(np - bridge_num[g]);
    }
    red[threadIdx.x] = d;
    __syncthreads();
    for (int s = 128; s > 0; s >>= 1) {
        if (threadIdx.x < s) red[threadIdx.x] += red[threadIdx.x + s];
        __syncthreads();
    }
    if (threadIdx.x == 0) atomicAdd(&g_acc[1], red[0]);
}

__global__ void apred_k(const int* __restrict__ bidx,
                        const float* __restrict__ bcp,
                        float* __restrict__ out, int P) {
    int p = blockIdx.x * 256 + threadIdx.x;
    if (p >= P) return;
    int i = __ldg(bidx + p);
    int j = __ldg(bidx + P + p);
    float logit = g_u[i] + g_v[j] + bcp[0];
    out[p] = 1.0f / (1.0f + expf(-logit));
}

__global__ void fin_k(float* __restrict__ out, int P, int N, int G) {
    out[P]     = 0.5f * g_acc[0] / ((float)N * (float)N);
    out[P + 1] = g_acc[1] / (float)G;
}

// ---------------------------------------------------------------------------
// Launcher
// ---------------------------------------------------------------------------
extern "C" void kernel_launch(void* const* d_in, const int* in_sizes, int n_in,
                              void* d_out, int out_size) {
    const float* x          = (const float*)d_in[0];
    const int*   ei         = (const int*)  d_in[1];
    const int*   batch      = (const int*)  d_in[2];
    const float* bridge_num = (const float*)d_in[3];
    const int*   bidx       = (const int*)  d_in[4];
    const float* noise      = (const float*)d_in[5];
    const float* W1s        = (const float*)d_in[6];
    const float* b1s        = (const float*)d_in[7];
    const float* gammas     = (const float*)d_in[8];
    const float* betas      = (const float*)d_in[9];
    const float* W2s        = (const float*)d_in[10];
    const float* b2s        = (const float*)d_in[11];
    const float* Wn         = (const float*)d_in[12];
    const float* bnp        = (const float*)d_in[13];
    const float* Wc         = (const float*)d_in[14];
    const float* bcp        = (const float*)d_in[15];
    float* out = (float*)d_out;

    int N = in_sizes[0] / 128;
    int E = in_sizes[1] / 2;
    int G = in_sizes[3];
    int P = in_sizes[4] / 2;

    float *agg, *ht, *h1, *h2, *mean, *ls, *colsum, *colsq, *pool, *cnt, *acc;
    cudaGetSymbolAddress((void**)&agg,    g_agg);
    cudaGetSymbolAddress((void**)&ht,     g_ht);
    cudaGetSymbolAddress((void**)&h1,     g_h1);
    cudaGetSymbolAddress((void**)&h2,     g_h2);
    cudaGetSymbolAddress((void**)&mean,   g_mean);
    cudaGetSymbolAddress((void**)&ls,     g_ls);
    cudaGetSymbolAddress((void**)&colsum, g_colsum);
    cudaGetSymbolAddress((void**)&colsq,  g_colsq);
    cudaGetSymbolAddress((void**)&pool,   g_pool);
    cudaGetSymbolAddress((void**)&cnt,    g_cnt);
    cudaGetSymbolAddress((void**)&acc,    g_acc);

    int rb = (N + BM - 1) / BM;          // 704 row blocks
    int scat_blocks = (E * 32 + 511) / 512;

    // ---- layer 0 ----
    cudaMemsetAsync(agg, 0, (size_t)N * 128 * sizeof(float));
    scatter_k<<<scat_blocks, 512>>>(x, ei, E);
    cudaMemsetAsync(colsum, 0, 512 * sizeof(float));
    cudaMemsetAsync(colsq,  0, 512 * sizeof(float));
    gemm1_k<<<dim3(2, rb), 256>>>(x, W1s, W1s, b1s, ht, N, 256);
    bnfin_k<<<1, 256>>>(gammas, betas, N);
    gemm2_k<<<dim3(1, rb), 256>>>(ht, W2s, b2s, h1, N, 256, 0, 1);

    // ---- layer 1 ----
    cudaMemsetAsync(agg, 0, (size_t)N * 128 * sizeof(float));
    scatter_k<<<scat_blocks, 512>>>(h1, ei, E);
    cudaMemsetAsync(colsum, 0, 512 * sizeof(float));
    cudaMemsetAsync(colsq,  0, 512 * sizeof(float));
    gemm1_k<<<dim3(2, rb), 256>>>(h1, W1s + 1 * 128 * 256, W1s, b1s + 256, ht, N, 256);
    bnfin_k<<<1, 256>>>(gammas + 256, betas + 256, N);
    gemm2_k<<<dim3(1, rb), 256>>>(ht, W2s + 1 * 256 * 128, b2s + 128, h2, N, 256, 0, 1);

    // ---- layers 2+3 combined (shared A = h2 + agg(h2)) ----
    cudaMemsetAsync(agg, 0, (size_t)N * 128 * sizeof(float));
    scatter_k<<<scat_blocks, 512>>>(h2, ei, E);
    cudaMemsetAsync(colsum, 0, 512 * sizeof(float));
    cudaMemsetAsync(colsq,  0, 512 * sizeof(float));
    gemm1_k<<<dim3(4, rb), 256>>>(h2, W1s + 2 * 128 * 256, W1s + 3 * 128 * 256,
                                  b1s + 512, ht, N, 512);
    bnfin_k<<<1, 512>>>(gammas + 512, betas + 512, N);
    gemm2_k<<<dim3(1, rb), 256>>>(ht, W2s + 2 * 256 * 128, b2s + 256, mean, N, 512, 0,   0);
    gemm2_k<<<dim3(1, rb), 256>>>(ht, W2s + 3 * 256 * 128, b2s + 384, ls,   N, 512, 256, 0);

    // ---- epilogue ----
    cudaMemsetAsync(pool, 0, G * sizeof(float));
    cudaMemsetAsync(cnt,  0, G * sizeof(float));
    cudaMemsetAsync(acc,  0, 2 * sizeof(float));
    z_k<<<(N + 7) / 8, 256>>>(mean, ls, noise, batch, Wn, Wc, N);
    num_k<<<(G + 255) / 256, 256>>>(bridge_num, bnp, out + P + 2, G);
    apred_k<<<(P + 255) / 256, 256>>>(bidx, bcp, out, P);
    fin_k<<<1, 1>>>(out, P, N, G);
}

// round 5
// speedup vs baseline: 1.0358x; 1.0358x over previous
#include <cuda_runtime.h>
#include <math.h>

// ---------------------------------------------------------------------------
// N=90000, D=H=128, 2H=256, E=1.44M, G=3000, P=675000.
// ---------------------------------------------------------------------------
#define MAXN 90112
#define MAXG 4096

__device__ float g_agg [MAXN * 128];
__device__ float g_ht  [MAXN * 512];
__device__ float g_h1  [MAXN * 128];
__device__ float g_h2  [MAXN * 128];
__device__ float g_mean[MAXN * 128];
__device__ float g_ls  [MAXN * 128];
__device__ float g_u   [MAXN];
__device__ float g_v   [MAXN];
__device__ float g_colsum[512];
__device__ float g_colsq [512];
__device__ float g_scale [512];
__device__ float g_shift [512];
__device__ float g_pool[MAXG];
__device__ float g_cnt [MAXG];
__device__ float g_acc [2];

__device__ __forceinline__ float f2tf(float f) {
    unsigned r;
    asm("cvt.rna.tf32.f32 %0, %1;" : "=r"(r) : "f"(f));
    return __uint_as_float(r);
}
__device__ __forceinline__ void mma_tf32(float4& d, const unsigned* a,
                                         unsigned b0, unsigned b1) {
    asm volatile(
        "mma.sync.aligned.m16n8k8.row.col.f32.tf32.tf32.f32 "
        "{%0,%1,%2,%3},{%4,%5,%6,%7},{%8,%9},{%0,%1,%2,%3};"
        : "+f"(d.x), "+f"(d.y), "+f"(d.z), "+f"(d.w)
        : "r"(a[0]), "r"(a[1]), "r"(a[2]), "r"(a[3]), "r"(b0), "r"(b1));
}

// ---------------------------------------------------------------------------
// Edge scatter: agg[dst] += x[src].  One warp per edge, vector red.
// ---------------------------------------------------------------------------
__global__ void scatter_k(const float* __restrict__ X,
                          const int* __restrict__ ei, int E) {
    int gw   = (blockIdx.x * blockDim.x + threadIdx.x) >> 5;
    int lane = threadIdx.x & 31;
    if (gw >= E) return;
    int s = __ldg(ei + gw);
    int d = __ldg(ei + E + gw);
    float4 vv = *(const float4*)(X + (size_t)s * 128 + lane * 4);
    float* dst = g_agg + (size_t)d * 128 + lane * 4;
    asm volatile("red.global.add.v4.f32 [%0], {%1,%2,%3,%4};"
                 :: "l"(dst), "f"(vv.x), "f"(vv.y), "f"(vv.z), "f"(vv.w)
                 : "memory");
}

// ---------------------------------------------------------------------------
// 3xTF32 tensor-core GEMM (error-compensated): acc = hi*hi + lo*hi + hi*lo.
// 128x128 block tile, 256 thr = 8 warps (4m x 2n), warp 32x64, m16n8k8.
// BK=16; 4 smem tiles (A hi/lo, B hi/lo), LD=136 -> conflict-free.
// ---------------------------------------------------------------------------
#define BM 128
#define BN 128
#define BK 16
#define LDS_ 136

#define SPLIT_STORE(ARR_HI, ARR_LO, K, M, V)                   \
    do { float _hi = f2tf(V);                                  \
         ARR_HI[K][M] = _hi;                                   \
         ARR_LO[K][M] = f2tf((V) - _hi); } while (0)

// GEMM1: OUT[:, n0:n0+128] = (X+agg) @ W + bias ; fused colsum/colsq stats.
__global__ void __launch_bounds__(256) gemm1_k(
    const float* __restrict__ X, const float* __restrict__ Wa,
    const float* __restrict__ Wb, const float* __restrict__ bias,
    float* __restrict__ OUT, int N, int ldo) {
    __shared__ float Ah[BK][LDS_], Al[BK][LDS_];
    __shared__ float Bh[BK][LDS_], Bl[BK][LDS_];
    int tid  = threadIdx.x;
    int row0 = blockIdx.y * BM;
    int n0   = blockIdx.x * BN;
    const float* W = (n0 < 256) ? Wa : Wb;
    int nbase = (n0 < 256) ? n0 : (n0 - 256);
    int lane = tid & 31, wid = tid >> 5;
    int lk = lane & 3, lm = lane >> 2;
    int warpM = wid & 3, warpN = wid >> 2;
    int mBase = warpM * 32, nBase = warpN * 64;
    float4 acc[2][8];
    #pragma unroll
    for (int i = 0; i < 2; i++)
        #pragma unroll
        for (int j = 0; j < 8; j++) acc[i][j] = make_float4(0.f,0.f,0.f,0.f);

    for (int kk = 0; kk < 128; kk += BK) {
        #pragma unroll
        for (int h = 0; h < 2; h++) {
            int idx = h * 256 + tid;
            int m = idx & 127, k = (idx >> 7) * 4;
            int rg = row0 + m;
            float4 a = make_float4(0.f,0.f,0.f,0.f);
            if (rg < N) {
                size_t off = (size_t)rg * 128 + kk + k;
                float4 xv = *(const float4*)(X + off);
                float4 av = *(const float4*)(g_agg + off);
                a.x = xv.x + av.x; a.y = xv.y + av.y;
                a.z = xv.z + av.z; a.w = xv.w + av.w;
            }
            SPLIT_STORE(Ah, Al, k+0, m, a.x);
            SPLIT_STORE(Ah, Al, k+1, m, a.y);
            SPLIT_STORE(Ah, Al, k+2, m, a.z);
            SPLIT_STORE(Ah, Al, k+3, m, a.w);
            int kb = idx >> 5, nc = (idx & 31) * 4;
            float4 w4 = *(const float4*)(W + (size_t)(kk + kb) * 256 + nbase + nc);
            SPLIT_STORE(Bh, Bl, kb, nc+0, w4.x);
            SPLIT_STORE(Bh, Bl, kb, nc+1, w4.y);
            SPLIT_STORE(Bh, Bl, kb, nc+2, w4.z);
            SPLIT_STORE(Bh, Bl, kb, nc+3, w4.w);
        }
        __syncthreads();
        #pragma unroll
        for (int s = 0; s < 2; s++) {
            int kr = s * 8 + lk;
            unsigned ah[2][4], al[2][4];
            #pragma unroll
            for (int wm = 0; wm < 2; wm++) {
                int mb = mBase + wm * 16 + lm;
                ah[wm][0] = __float_as_uint(Ah[kr][mb]);
                ah[wm][1] = __float_as_uint(Ah[kr][mb + 8]);
                ah[wm][2] = __float_as_uint(Ah[kr+4][mb]);
                ah[wm][3] = __float_as_uint(Ah[kr+4][mb + 8]);
                al[wm][0] = __float_as_uint(Al[kr][mb]);
                al[wm][1] = __float_as_uint(Al[kr][mb + 8]);
                al[wm][2] = __float_as_uint(Al[kr+4][mb]);
                al[wm][3] = __float_as_uint(Al[kr+4][mb + 8]);
            }
            #pragma unroll
            for (int wn = 0; wn < 8; wn++) {
                int nb = nBase + wn * 8 + lm;
                unsigned bh0 = __float_as_uint(Bh[kr][nb]);
                unsigned bh1 = __float_as_uint(Bh[kr+4][nb]);
                unsigned bl0 = __float_as_uint(Bl[kr][nb]);
                unsigned bl1 = __float_as_uint(Bl[kr+4][nb]);
                #pragma unroll
                for (int wm = 0; wm < 2; wm++) {
                    mma_tf32(acc[wm][wn], ah[wm], bh0, bh1);
                    mma_tf32(acc[wm][wn], al[wm], bh0, bh1);
                    mma_tf32(acc[wm][wn], ah[wm], bl0, bl1);
                }
            }
        }
        __syncthreads();
    }

    // epilogue: bias, store, per-column stats
    float psx[8]={}, psy[8]={}, pqx[8]={}, pqy[8]={};
    #pragma unroll
    for (int wn = 0; wn < 8; wn++) {
        int col = n0 + nBase + wn * 8 + 2 * lk;
        float bx = bias[col], by = bias[col + 1];
        #pragma unroll
        for (int wm = 0; wm < 2; wm++) {
            float4 d = acc[wm][wn];
            int ra = row0 + mBase + wm * 16 + lm;
            int rb = ra + 8;
            float ox = d.x + bx, oy = d.y + by;
            float oz = d.z + bx, ow = d.w + by;
            if (ra < N) {
                *(float2*)(OUT + (size_t)ra * ldo + col) = make_float2(ox, oy);
                psx[wn] += ox; psy[wn] += oy;
                pqx[wn] += ox * ox; pqy[wn] += oy * oy;
            }
            if (rb < N) {
                *(float2*)(OUT + (size_t)rb * ldo + col) = make_float2(oz, ow);
                psx[wn] += oz; psy[wn] += ow;
                pqx[wn] += oz * oz; pqy[wn] += ow * ow;
            }
        }
    }
    #pragma unroll
    for (int wn = 0; wn < 8; wn++) {
        #pragma unroll
        for (int o = 4; o <= 16; o <<= 1) {
            psx[wn] += __shfl_xor_sync(0xffffffffu, psx[wn], o);
            psy[wn] += __shfl_xor_sync(0xffffffffu, psy[wn], o);
            pqx[wn] += __shfl_xor_sync(0xffffffffu, pqx[wn], o);
            pqy[wn] += __shfl_xor_sync(0xffffffffu, pqy[wn], o);
        }
    }
    if (lane < 4) {
        #pragma unroll
        for (int wn = 0; wn < 8; wn++) {
            int col = n0 + nBase + wn * 8 + 2 * lane;
            atomicAdd(&g_colsum[col],     psx[wn]);
            atomicAdd(&g_colsum[col + 1], psy[wn]);
            atomicAdd(&g_colsq[col],      pqx[wn]);
            atomicAdd(&g_colsq[col + 1],  pqy[wn]);
        }
    }
}

__global__ void bnfin_k(const float* __restrict__ gamma,
                        const float* __restrict__ beta, int N) {
    int c = blockIdx.x * blockDim.x + threadIdx.x;
    float invN = 1.0f / (float)N;
    float mu  = g_colsum[c] * invN;
    float var = g_colsq[c] * invN - mu * mu;
    float sc  = gamma[c] * rsqrtf(var + 1e-5f);
    g_scale[c] = sc;
    g_shift[c] = beta[c] - mu * sc;
}

// GEMM2: OUT[N,128] = BN(HT[:,koff:koff+256]) [relu] @ W[256,128] + b2
__global__ void __launch_bounds__(256) gemm2_k(
    const float* __restrict__ HT, const float* __restrict__ W,
    const float* __restrict__ bias, float* __restrict__ OUT,
    int N, int ldh, int koff, int relu) {
    __shared__ float Ah[BK][LDS_], Al[BK][LDS_];
    __shared__ float Bh[BK][LDS_], Bl[BK][LDS_];
    int tid  = threadIdx.x;
    int row0 = blockIdx.y * BM;
    int n0   = blockIdx.x * BN;
    int lane = tid & 31, wid = tid >> 5;
    int lk = lane & 3, lm = lane >> 2;
    int warpM = wid & 3, warpN = wid >> 2;
    int mBase = warpM * 32, nBase = warpN * 64;
    float4 acc[2][8];
    #pragma unroll
    for (int i = 0; i < 2; i++)
        #pragma unroll
        for (int j = 0; j < 8; j++) acc[i][j] = make_float4(0.f,0.f,0.f,0.f);

    for (int kk = 0; kk < 256; kk += BK) {
        #pragma unroll
        for (int h = 0; h < 2; h++) {
            int idx = h * 256 + tid;
            int m = idx & 127, k = (idx >> 7) * 4;
            int rg = row0 + m;
            float4 a = make_float4(0.f,0.f,0.f,0.f);
            if (rg < N) {
                float4 h4 = *(const float4*)(HT + (size_t)rg * ldh + koff + kk + k);
                float4 sc4 = *(const float4*)(g_scale + koff + kk + k);
                float4 sh4 = *(const float4*)(g_shift + koff + kk + k);
                a.x = h4.x * sc4.x + sh4.x;
                a.y = h4.y * sc4.y + sh4.y;
                a.z = h4.z * sc4.z + sh4.z;
                a.w = h4.w * sc4.w + sh4.w;
                if (relu) {
                    a.x = fmaxf(a.x, 0.f); a.y = fmaxf(a.y, 0.f);
                    a.z = fmaxf(a.z, 0.f); a.w = fmaxf(a.w, 0.f);
                }
            }
            SPLIT_STORE(Ah, Al, k+0, m, a.x);
            SPLIT_STORE(Ah, Al, k+1, m, a.y);
            SPLIT_STORE(Ah, Al, k+2, m, a.z);
            SPLIT_STORE(Ah, Al, k+3, m, a.w);
            int kb = idx >> 5, nc = (idx & 31) * 4;
            float4 w4 = *(const float4*)(W + (size_t)(kk + kb) * 128 + n0 + nc);
            SPLIT_STORE(Bh, Bl, kb, nc+0, w4.x);
            SPLIT_STORE(Bh, Bl, kb, nc+1, w4.y);
            SPLIT_STORE(Bh, Bl, kb, nc+2, w4.z);
            SPLIT_STORE(Bh, Bl, kb, nc+3, w4.w);
        }
        __syncthreads();
        #pragma unroll
        for (int s = 0; s < 2; s++) {
            int kr = s * 8 + lk;
            unsigned ah[2][4], al[2][4];
            #pragma unroll
            for (int wm = 0; wm < 2; wm++) {
                int mb = mBase + wm * 16 + lm;
                ah[wm][0] = __float_as_uint(Ah[kr][mb]);
                ah[wm][1] = __float_as_uint(Ah[kr][mb + 8]);
                ah[wm][2] = __float_as_uint(Ah[kr+4][mb]);
                ah[wm][3] = __float_as_uint(Ah[kr+4][mb + 8]);
                al[wm][0] = __float_as_uint(Al[kr][mb]);
                al[wm][1] = __float_as_uint(Al[kr][mb + 8]);
                al[wm][2] = __float_as_uint(Al[kr+4][mb]);
                al[wm][3] = __float_as_uint(Al[kr+4][mb + 8]);
            }
            #pragma unroll
            for (int wn = 0; wn < 8; wn++) {
                int nb = nBase + wn * 8 + lm;
                unsigned bh0 = __float_as_uint(Bh[kr][nb]);
                unsigned bh1 = __float_as_uint(Bh[kr+4][nb]);
                unsigned bl0 = __float_as_uint(Bl[kr][nb]);
                unsigned bl1 = __float_as_uint(Bl[kr+4][nb]);
                #pragma unroll
                for (int wm = 0; wm < 2; wm++) {
                    mma_tf32(acc[wm][wn], ah[wm], bh0, bh1);
                    mma_tf32(acc[wm][wn], al[wm], bh0, bh1);
                    mma_tf32(acc[wm][wn], ah[wm], bl0, bl1);
                }
            }
        }
        __syncthreads();
    }

    #pragma unroll
    for (int wn = 0; wn < 8; wn++) {
        int col = n0 + nBase + wn * 8 + 2 * lk;
        float bx = bias[col], by = bias[col + 1];
        #pragma unroll
        for (int wm = 0; wm < 2; wm++) {
            float4 d = acc[wm][wn];
            int ra = row0 + mBase + wm * 16 + lm;
            int rb = ra + 8;
            if (ra < N)
                *(float2*)(OUT + (size_t)ra * 128 + col) = make_float2(d.x + bx, d.y + by);
            if (rb < N)
                *(float2*)(OUT + (size_t)rb * 128 + col) = make_float2(d.z + bx, d.w + by);
        }
    }
}

// ---------------------------------------------------------------------------
// z epilogue and small kernels.
// ---------------------------------------------------------------------------
__global__ void z_k(const float* __restrict__ MEAN, const float* __restrict__ LS,
                    const float* __restrict__ NOISE, const int* __restrict__ batch,
                    const float* __restrict__ Wn, const float* __restrict__ Wc,
                    int N) {
    __shared__ float klred[8];
    int lane = threadIdx.x & 31;
    int w    = threadIdx.x >> 5;
    int row  = blockIdx.x * 8 + w;
    float klp = 0.f;
    if (row < N) {
        size_t off = (size_t)row * 128 + lane * 4;
        float4 m4 = *(const float4*)(MEAN + off);
        float4 l4 = *(const float4*)(LS + off);
        float4 n4 = *(const float4*)(NOISE + off);
        float4 e4 = make_float4(expf(l4.x), expf(l4.y), expf(l4.z), expf(l4.w));
        float4 z4 = make_float4(n4.x * e4.x + m4.x, n4.y * e4.y + m4.y,
                                n4.z * e4.z + m4.z, n4.w * e4.w + m4.w);
        float4 wa = *(const float4*)(Wc + lane * 4);
        float4 wb = *(const float4*)(Wc + 128 + lane * 4);
        float4 wn = *(const float4*)(Wn + lane * 4);
        float up = z4.x * wa.x + z4.y * wa.y + z4.z * wa.z + z4.w * wa.w;
        float vp = z4.x * wb.x + z4.y * wb.y + z4.z * wb.z + z4.w * wb.w;
        float sp = z4.x * wn.x + z4.y * wn.y + z4.z * wn.z + z4.w * wn.w;
        klp = (1.f + 2.f * l4.x - m4.x * m4.x - e4.x * e4.x)
            + (1.f + 2.f * l4.y - m4.y * m4.y - e4.y * e4.y)
            + (1.f + 2.f * l4.z - m4.z * m4.z - e4.z * e4.z)
            + (1.f + 2.f * l4.w - m4.w * m4.w - e4.w * e4.w);
        #pragma unroll
        for (int o = 16; o > 0; o >>= 1) {
            up  += __shfl_xor_sync(0xffffffffu, up,  o);
            vp  += __shfl_xor_sync(0xffffffffu, vp,  o);
            sp  += __shfl_xor_sync(0xffffffffu, sp,  o);
            klp += __shfl_xor_sync(0xffffffffu, klp, o);
        }
        if (lane == 0) {
            g_u[row] = up;
            g_v[row] = vp;
            int b = batch[row];
            atomicAdd(&g_pool[b], sp);
            atomicAdd(&g_cnt[b], 1.0f);
        }
    }
    if (lane == 0) klred[w] = (row < N) ? klp : 0.f;
    __syncthreads();
    if (threadIdx.x == 0) {
        float t = 0.f;
        #pragma unroll
        for (int i = 0; i < 8; i++) t += klred[i];
        atomicAdd(&g_acc[0], t);
    }
}

__global__ void num_k(const float* __restrict__ bridge_num,
                      const float* __restrict__ bnp,
                      float* __restrict__ out_np, int G) {
    __shared__ float red[256];
    int g = blockIdx.x * 256 + threadIdx.x;
    float d = 0.f;
    if (g < G) {
        float np = g_pool[g] / g_cnt[g] + bnp[0];
        out_np[g] = np;
        d = fabsf(np - bridge_num[g]);
    }
    red[threadIdx.x] = d;
    __syncthreads();
    for (int s = 128; s > 0; s >>= 1) {
        if (threadIdx.x < s) red[threadIdx.x] += red[threadIdx.x + s];
        __syncthreads();
    }
    if (threadIdx.x == 0) atomicAdd(&g_acc[1], red[0]);
}

__global__ void apred_k(const int* __restrict__ bidx,
                        const float* __restrict__ bcp,
                        float* __restrict__ out, int P) {
    int p = blockIdx.x * 256 + threadIdx.x;
    if (p >= P) return;
    int i = __ldg(bidx + p);
    int j = __ldg(bidx + P + p);
    float logit = g_u[i] + g_v[j] + bcp[0];
    out[p] = 1.0f / (1.0f + expf(-logit));
}

__global__ void fin_k(float* __restrict__ out, int P, int N, int G) {
    out[P]     = 0.5f * g_acc[0] / ((float)N * (float)N);
    out[P + 1] = g_acc[1] / (float)G;
}

// ---------------------------------------------------------------------------
// Launcher
// ---------------------------------------------------------------------------
extern "C" void kernel_launch(void* const* d_in, const int* in_sizes, int n_in,
                              void* d_out, int out_size) {
    const float* x          = (const float*)d_in[0];
    const int*   ei         = (const int*)  d_in[1];
    const int*   batch      = (const int*)  d_in[2];
    const float* bridge_num = (const float*)d_in[3];
    const int*   bidx       = (const int*)  d_in[4];
    const float* noise      = (const float*)d_in[5];
    const float* W1s        = (const float*)d_in[6];
    const float* b1s        = (const float*)d_in[7];
    const float* gammas     = (const float*)d_in[8];
    const float* betas      = (const float*)d_in[9];
    const float* W2s        = (const float*)d_in[10];
    const float* b2s        = (const float*)d_in[11];
    const float* Wn         = (const float*)d_in[12];
    const float* bnp        = (const float*)d_in[13];
    const float* Wc         = (const float*)d_in[14];
    const float* bcp        = (const float*)d_in[15];
    float* out = (float*)d_out;

    int N = in_sizes[0] / 128;
    int E = in_sizes[1] / 2;
    int G = in_sizes[3];
    int P = in_sizes[4] / 2;

    float *agg, *ht, *h1, *h2, *mean, *ls, *colsum, *colsq, *pool, *cnt, *acc;
    cudaGetSymbolAddress((void**)&agg,    g_agg);
    cudaGetSymbolAddress((void**)&ht,     g_ht);
    cudaGetSymbolAddress((void**)&h1,     g_h1);
    cudaGetSymbolAddress((void**)&h2,     g_h2);
    cudaGetSymbolAddress((void**)&mean,   g_mean);
    cudaGetSymbolAddress((void**)&ls,     g_ls);
    cudaGetSymbolAddress((void**)&colsum, g_colsum);
    cudaGetSymbolAddress((void**)&colsq,  g_colsq);
    cudaGetSymbolAddress((void**)&pool,   g_pool);
    cudaGetSymbolAddress((void**)&cnt,    g_cnt);
    cudaGetSymbolAddress((void**)&acc,    g_acc);

    int rb = (N + BM - 1) / BM;
    int scat_blocks = (E * 32 + 511) / 512;

    // ---- layer 0 ----
    cudaMemsetAsync(agg, 0, (size_t)N * 128 * sizeof(float));
    scatter_k<<<scat_blocks, 512>>>(x, ei, E);
    cudaMemsetAsync(colsum, 0, 512 * sizeof(float));
    cudaMemsetAsync(colsq,  0, 512 * sizeof(float));
    gemm1_k<<<dim3(2, rb), 256>>>(x, W1s, W1s, b1s, ht, N, 256);
    bnfin_k<<<1, 256>>>(gammas, betas, N);
    gemm2_k<<<dim3(1, rb), 256>>>(ht, W2s, b2s, h1, N, 256, 0, 1);

    // ---- layer 1 ----
    cudaMemsetAsync(agg, 0, (size_t)N * 128 * sizeof(float));
    scatter_k<<<scat_blocks, 512>>>(h1, ei, E);
    cudaMemsetAsync(colsum, 0, 512 * sizeof(float));
    cudaMemsetAsync(colsq,  0, 512 * sizeof(float));
    gemm1_k<<<dim3(2, rb), 256>>>(h1, W1s + 1 * 128 * 256, W1s, b1s + 256, ht, N, 256);
    bnfin_k<<<1, 256>>>(gammas + 256, betas + 256, N);
    gemm2_k<<<dim3(1, rb), 256>>>(ht, W2s + 1 * 256 * 128, b2s + 128, h2, N, 256, 0, 1);

    // ---- layers 2+3 combined (shared A = h2 + agg(h2)) ----
    cudaMemsetAsync(agg, 0, (size_t)N * 128 * sizeof(float));
    scatter_k<<<scat_blocks, 512>>>(h2, ei, E);
    cudaMemsetAsync(colsum, 0, 512 * sizeof(float));
    cudaMemsetAsync(colsq,  0, 512 * sizeof(float));
    gemm1_k<<<dim3(4, rb), 256>>>(h2, W1s + 2 * 128 * 256, W1s + 3 * 128 * 256,
                                  b1s + 512, ht, N, 512);
    bnfin_k<<<1, 512>>>(gammas + 512, betas + 512, N);
    gemm2_k<<<dim3(1, rb), 256>>>(ht, W2s + 2 * 256 * 128, b2s + 256, mean, N, 512, 0,   0);
    gemm2_k<<<dim3(1, rb), 256>>>(ht, W2s + 3 * 256 * 128, b2s + 384, ls,   N, 512, 256, 0);

    // ---- epilogue ----
    cudaMemsetAsync(pool, 0, G * sizeof(float));
    cudaMemsetAsync(cnt,  0, G * sizeof(float));
    cudaMemsetAsync(acc,  0, 2 * sizeof(float));
    z_k<<<(N + 7) / 8, 256>>>(mean, ls, noise, batch, Wn, Wc, N);
    num_k<<<(G + 255) / 256, 256>>>(bridge_num, bnp, out + P + 2, G);
    apred_k<<<(P + 255) / 256, 256>>>(bidx, bcp, out, P);
    fin_k<<<1, 1>>>(out, P, N, G);
}